// round 1
// baseline (speedup 1.0000x reference)
#include <cuda_runtime.h>
#include <cstdint>

#define NNODES 50000
#define NREL   3
#define NEDGE  600000
#define FIN1   128
#define FHID   64

// ---------------- scratch (no allocs allowed) ----------------
__device__ float g_H[(size_t)NREL * NNODES * FHID];   // per-relation GEMM output (38.4MB)
__device__ float g_h1[(size_t)NNODES * FHID];         // layer-1 activations / layer-1 agg
__device__ float g_onorm[NREL * NNODES];
__device__ float g_inorm[NREL * NNODES];
__device__ int   g_odeg[NREL * NNODES];
__device__ int   g_ideg[NREL * NNODES];

// ---------------- kernels ----------------

__global__ void zero_kernel(float* __restrict__ out, int N) {
    int i = blockIdx.x * blockDim.x + threadIdx.x;
    int tot = N * FHID;
    if (i < tot) { out[i] = 0.0f; g_h1[i] = 0.0f; }
    if (i < NREL * N) { g_odeg[i] = 0; g_ideg[i] = 0; }
}

__global__ void deg_kernel(const int* __restrict__ src, const int* __restrict__ dst,
                           int E, int N) {
    int e = blockIdx.x * blockDim.x + threadIdx.x;
    if (e >= NREL * E) return;
    int r = (e >= E) + (e >= 2 * E);
    atomicAdd(&g_odeg[r * N + src[e]], 1);
    atomicAdd(&g_ideg[r * N + dst[e]], 1);
}

__global__ void norm_kernel(int M) {
    int i = blockIdx.x * blockDim.x + threadIdx.x;
    if (i >= M) return;
    int od = g_odeg[i]; if (od < 1) od = 1;
    int id = g_ideg[i]; if (id < 1) id = 1;
    g_onorm[i] = rsqrtf((float)od);
    g_inorm[i] = rsqrtf((float)id);
}

// H[r][row][:] = onorm[r][row] * (X[row][:] @ W[r])
// grid: (ceil(N/64), NREL), block 256. Tile: 64 rows x 64 cols, K chunked by 64.
template <int FIN>
__global__ void gemm_kernel(const float* __restrict__ X, const float* __restrict__ W,
                            float* __restrict__ Hout, int N) {
    constexpr int TK = 64;
    constexpr int XP = 68;                 // padded row stride (bank-conflict-free, 16B aligned)
    __shared__ float sX[64 * XP];
    __shared__ float sW[TK * 64];

    const int r    = blockIdx.y;
    const int row0 = blockIdx.x * 64;
    const int tid  = threadIdx.x;
    const int rg   = tid >> 4;             // 0..15 -> 4 rows each
    const int cg   = tid & 15;             // 0..15 -> 4 cols each

    float acc[4][4] = {};

    for (int kt = 0; kt < FIN; kt += TK) {
        // load W chunk [TK x 64] (contiguous)
        const float4* Wr = (const float4*)(W + ((size_t)r * FIN + kt) * 64);
        #pragma unroll
        for (int i = tid; i < TK * 16; i += 256) ((float4*)sW)[i] = Wr[i];
        // load X chunk [64 rows x TK]
        #pragma unroll
        for (int i = tid; i < 64 * 16; i += 256) {
            int row = i >> 4, c4 = i & 15;
            int grow = row0 + row;
            float4 v = make_float4(0.f, 0.f, 0.f, 0.f);
            if (grow < N) v = ((const float4*)(X + (size_t)grow * FIN + kt))[c4];
            ((float4*)(sX + row * XP))[c4] = v;
        }
        __syncthreads();

        #pragma unroll 8
        for (int k = 0; k < TK; k++) {
            float a0 = sX[(rg * 4 + 0) * XP + k];
            float a1 = sX[(rg * 4 + 1) * XP + k];
            float a2 = sX[(rg * 4 + 2) * XP + k];
            float a3 = sX[(rg * 4 + 3) * XP + k];
            float4 b = ((float4*)(sW + k * 64))[cg];
            acc[0][0] += a0 * b.x; acc[0][1] += a0 * b.y; acc[0][2] += a0 * b.z; acc[0][3] += a0 * b.w;
            acc[1][0] += a1 * b.x; acc[1][1] += a1 * b.y; acc[1][2] += a1 * b.z; acc[1][3] += a1 * b.w;
            acc[2][0] += a2 * b.x; acc[2][1] += a2 * b.y; acc[2][2] += a2 * b.z; acc[2][3] += a2 * b.w;
            acc[3][0] += a3 * b.x; acc[3][1] += a3 * b.y; acc[3][2] += a3 * b.z; acc[3][3] += a3 * b.w;
        }
        __syncthreads();
    }

    #pragma unroll
    for (int i = 0; i < 4; i++) {
        int grow = row0 + rg * 4 + i;
        if (grow < N) {
            float s = g_onorm[r * N + grow];
            float4 v = make_float4(acc[i][0] * s, acc[i][1] * s, acc[i][2] * s, acc[i][3] * s);
            ((float4*)(Hout + ((size_t)r * N + grow) * 64))[cg] = v;
        }
    }
}

__device__ __forceinline__ void red_add_v4(float* p, float a, float b, float c, float d) {
    asm volatile("red.global.add.v4.f32 [%0], {%1,%2,%3,%4};"
                 :: "l"(p), "f"(a), "f"(b), "f"(c), "f"(d) : "memory");
}

// acc[dst] += H[r][src] * in_norm_r[dst]  -- 16 lanes per edge (one float4 each)
__global__ void scatter_kernel(const float* __restrict__ H,
                               const int* __restrict__ src, const int* __restrict__ dst,
                               float* __restrict__ acc, int E, int N) {
    int t = blockIdx.x * blockDim.x + threadIdx.x;
    int e = t >> 4;
    if (e >= NREL * E) return;
    int lane = t & 15;
    int r = (e >= E) + (e >= 2 * E);
    int s = src[e];
    int d = dst[e];
    float nrm = __ldg(&g_inorm[r * N + d]);
    float4 v = __ldg(((const float4*)(H + ((size_t)r * N + s) * 64)) + lane);
    red_add_v4(acc + (size_t)d * 64 + lane * 4, v.x * nrm, v.y * nrm, v.z * nrm, v.w * nrm);
}

// h[n][c] = (relu?) (h[n][c] + sum_r b[r][c])
__global__ void bias_kernel(float* __restrict__ h, const float* __restrict__ b,
                            int N, int do_relu) {
    int i = blockIdx.x * blockDim.x + threadIdx.x;
    if (i >= N * 16) return;
    int c = (i & 15) * 4;
    float4 v = ((float4*)h)[i];
    v.x += b[c + 0] + b[64 + c + 0] + b[128 + c + 0];
    v.y += b[c + 1] + b[64 + c + 1] + b[128 + c + 1];
    v.z += b[c + 2] + b[64 + c + 2] + b[128 + c + 2];
    v.w += b[c + 3] + b[64 + c + 3] + b[128 + c + 3];
    if (do_relu) {
        v.x = fmaxf(v.x, 0.f); v.y = fmaxf(v.y, 0.f);
        v.z = fmaxf(v.z, 0.f); v.w = fmaxf(v.w, 0.f);
    }
    ((float4*)h)[i] = v;
}

// ---------------- launch ----------------
extern "C" void kernel_launch(void* const* d_in, const int* in_sizes, int n_in,
                              void* d_out, int out_size) {
    const float* x   = (const float*)d_in[0];
    const float* W1  = (const float*)d_in[1];
    const float* b1  = (const float*)d_in[2];
    const float* W2  = (const float*)d_in[3];
    const float* b2  = (const float*)d_in[4];
    const int*   src = (const int*)d_in[5];
    const int*   dst = (const int*)d_in[6];
    float* out = (float*)d_out;

    const int N = in_sizes[0] / FIN1;      // 50000
    const int E = in_sizes[5] / NREL;      // 600000

    float *Hp, *h1p;
    cudaGetSymbolAddress((void**)&Hp,  g_H);
    cudaGetSymbolAddress((void**)&h1p, g_h1);

    // init: zero out/acc/degrees, compute degrees + norms (shared by both layers)
    zero_kernel<<<(N * FHID + 255) / 256, 256>>>(out, N);
    deg_kernel<<<(NREL * E + 255) / 256, 256>>>(src, dst, E, N);
    norm_kernel<<<(NREL * N + 255) / 256, 256>>>(NREL * N);

    dim3 gemm_grid((N + 63) / 64, NREL);
    int  edge_threads = NREL * E * 16;

    // layer 1
    gemm_kernel<FIN1><<<gemm_grid, 256>>>(x, W1, Hp, N);
    scatter_kernel<<<(edge_threads + 255) / 256, 256>>>(Hp, src, dst, h1p, E, N);
    bias_kernel<<<(N * 16 + 255) / 256, 256>>>(h1p, b1, N, 1);

    // layer 2
    gemm_kernel<FHID><<<gemm_grid, 256>>>(h1p, W2, Hp, N);
    scatter_kernel<<<(edge_threads + 255) / 256, 256>>>(Hp, src, dst, out, E, N);
    bias_kernel<<<(N * 16 + 255) / 256, 256>>>(out, b2, N, 0);
}

// round 2
// speedup vs baseline: 1.2406x; 1.2406x over previous
#include <cuda_runtime.h>
#include <cstdint>

#define NNODES 50000
#define NREL   3
#define NEDGE  600000
#define FIN1   128
#define FHID   64
#define M_SEG  (NREL * NNODES)      // 150000 segments

// ---------------- scratch (no allocs allowed) ----------------
__device__ __align__(128) float g_H[(size_t)NREL * NNODES * FHID]; // per-rel GEMM out (38.4MB)
__device__ __align__(128) float g_h1[(size_t)NNODES * FHID];       // layer-1 activations
__device__ int g_odeg[M_SEG];
__device__ int g_ideg[M_SEG];
__device__ int g_off[M_SEG + 1];     // CSR offsets (by dst, per relation)
__device__ int g_cursor[M_SEG];
__device__ int g_eidx[NREL * NEDGE]; // src node per CSR slot
__device__ int g_bsum[256];          // block sums for scan

// ---------------- degree / CSR build ----------------

__global__ void zero_kernel() {
    int i = blockIdx.x * blockDim.x + threadIdx.x;
    if (i < M_SEG) { g_odeg[i] = 0; g_ideg[i] = 0; }
}

__global__ void deg_kernel(const int* __restrict__ src, const int* __restrict__ dst,
                           int E, int N) {
    int e = blockIdx.x * blockDim.x + threadIdx.x;
    if (e >= NREL * E) return;
    int r = (e >= E) + (e >= 2 * E);
    atomicAdd(&g_odeg[r * N + src[e]], 1);
    atomicAdd(&g_ideg[r * N + dst[e]], 1);
}

// scan phase 1: per-1024-element block exclusive scan + block sums
__global__ void scan1_kernel() {
    __shared__ int sh[256];
    int t = threadIdx.x;
    int base = blockIdx.x * 1024 + t * 4;
    int v0 = (base + 0 < M_SEG) ? g_ideg[base + 0] : 0;
    int v1 = (base + 1 < M_SEG) ? g_ideg[base + 1] : 0;
    int v2 = (base + 2 < M_SEG) ? g_ideg[base + 2] : 0;
    int v3 = (base + 3 < M_SEG) ? g_ideg[base + 3] : 0;
    int t0 = v0, t1 = t0 + v1, t2 = t1 + v2, t3 = t2 + v3;
    sh[t] = t3;
    __syncthreads();
    for (int off = 1; off < 256; off <<= 1) {
        int x = (t >= off) ? sh[t - off] : 0;
        __syncthreads();
        sh[t] += x;
        __syncthreads();
    }
    int excl = (t > 0) ? sh[t - 1] : 0;
    if (base + 0 < M_SEG) g_off[base + 0] = excl;
    if (base + 1 < M_SEG) g_off[base + 1] = excl + t0;
    if (base + 2 < M_SEG) g_off[base + 2] = excl + t1;
    if (base + 3 < M_SEG) g_off[base + 3] = excl + t2;
    if (t == 255) g_bsum[blockIdx.x] = sh[255];
}

// scan phase 2: exclusive scan of block sums (single block, B <= 256)
__global__ void scan2_kernel(int B) {
    __shared__ int sh[256];
    int t = threadIdx.x;
    sh[t] = (t < B) ? g_bsum[t] : 0;
    __syncthreads();
    for (int off = 1; off < 256; off <<= 1) {
        int x = (t >= off) ? sh[t - off] : 0;
        __syncthreads();
        sh[t] += x;
        __syncthreads();
    }
    int excl = (t > 0) ? sh[t - 1] : 0;
    if (t < B) g_bsum[t] = excl;
}

// scan phase 3: add block bases; init cursor; write sentinel
__global__ void scan3_kernel(int totalE) {
    int i = blockIdx.x * blockDim.x + threadIdx.x;
    if (i < M_SEG) {
        int v = g_off[i] + g_bsum[i >> 10];
        g_off[i] = v;
        g_cursor[i] = v;
    }
    if (i == 0) g_off[M_SEG] = totalE;
}

__global__ void fill_kernel(const int* __restrict__ src, const int* __restrict__ dst,
                            int E, int N) {
    int e = blockIdx.x * blockDim.x + threadIdx.x;
    if (e >= NREL * E) return;
    int r = (e >= E) + (e >= 2 * E);
    int pos = atomicAdd(&g_cursor[r * N + dst[e]], 1);
    g_eidx[pos] = src[e];
}

// ---------------- GEMM: H[r][row] = rsqrt(odeg) * (X[row] @ W[r]) ----------------
// tile 128 rows x 64 cols, 128 threads, 8x8 per thread, K chunked by 32
template <int FIN>
__global__ void gemm_kernel(const float* __restrict__ X, const float* __restrict__ W,
                            float* __restrict__ Hout, int N) {
    constexpr int TK = 32;
    constexpr int XS = TK + 4;  // 36 floats/row, float4-aligned
    __shared__ float sX[128 * XS];
    __shared__ float sW[TK * 64];

    const int r    = blockIdx.y;
    const int row0 = blockIdx.x * 128;
    const int tid  = threadIdx.x;     // 0..127
    const int tc   = tid & 7;         // 8 col-groups of 8 cols
    const int tr   = tid >> 3;        // 0..15, rows tr + 16*i

    float acc[8][8] = {};

    for (int kt = 0; kt < FIN; kt += TK) {
        // W chunk [TK x 64] contiguous: 512 float4
        const float4* Wg = (const float4*)(W + ((size_t)r * FIN + kt) * 64);
        #pragma unroll
        for (int i = tid; i < TK * 16; i += 128) ((float4*)sW)[i] = Wg[i];
        // X chunk [128 rows x TK]: 8 float4 per row
        #pragma unroll
        for (int i = tid; i < 128 * (TK / 4); i += 128) {
            int row = i >> 3, c4 = i & 7;
            int grow = row0 + row;
            float4 v = make_float4(0.f, 0.f, 0.f, 0.f);
            if (grow < N) v = __ldg((const float4*)(X + (size_t)grow * FIN + kt) + c4);
            *(float4*)(sX + row * XS + c4 * 4) = v;
        }
        __syncthreads();

        #pragma unroll
        for (int k = 0; k < TK; k++) {
            float a[8];
            #pragma unroll
            for (int i = 0; i < 8; i++) a[i] = sX[(tr + 16 * i) * XS + k];
            float4 b0 = *(const float4*)(sW + k * 64 + tc * 8);
            float4 b1 = *(const float4*)(sW + k * 64 + tc * 8 + 4);
            #pragma unroll
            for (int i = 0; i < 8; i++) {
                acc[i][0] += a[i] * b0.x; acc[i][1] += a[i] * b0.y;
                acc[i][2] += a[i] * b0.z; acc[i][3] += a[i] * b0.w;
                acc[i][4] += a[i] * b1.x; acc[i][5] += a[i] * b1.y;
                acc[i][6] += a[i] * b1.z; acc[i][7] += a[i] * b1.w;
            }
        }
        __syncthreads();
    }

    #pragma unroll
    for (int i = 0; i < 8; i++) {
        int grow = row0 + tr + 16 * i;
        if (grow < N) {
            int od = g_odeg[r * N + grow];
            float s = rsqrtf((float)(od < 1 ? 1 : od));
            float4* o = (float4*)(Hout + ((size_t)r * N + grow) * 64 + tc * 8);
            o[0] = make_float4(acc[i][0] * s, acc[i][1] * s, acc[i][2] * s, acc[i][3] * s);
            o[1] = make_float4(acc[i][4] * s, acc[i][5] * s, acc[i][6] * s, acc[i][7] * s);
        }
    }
}

// ---------------- gather-aggregate (CSR), fused norm+bias+relu ----------------
// one warp per node; lane owns 2 channels (float2)
__global__ void gather_kernel(const float* __restrict__ H, const float* __restrict__ bias,
                              float* __restrict__ out, int N, int do_relu) {
    int warp = (blockIdx.x * blockDim.x + threadIdx.x) >> 5;
    int lane = threadIdx.x & 31;
    if (warp >= N) return;
    const int n = warp;

    float ax = 0.f, ay = 0.f;
    #pragma unroll
    for (int r = 0; r < NREL; r++) {
        const float* Hr = H + (size_t)r * N * 64 + lane * 2;
        int beg = g_off[r * N + n];
        int end = g_off[r * N + n + 1];
        float sx = 0.f, sy = 0.f;
        int i = beg;
        for (; i + 4 <= end; i += 4) {
            int s0 = g_eidx[i], s1 = g_eidx[i + 1], s2 = g_eidx[i + 2], s3 = g_eidx[i + 3];
            float2 v0 = *(const float2*)(Hr + (size_t)s0 * 64);
            float2 v1 = *(const float2*)(Hr + (size_t)s1 * 64);
            float2 v2 = *(const float2*)(Hr + (size_t)s2 * 64);
            float2 v3 = *(const float2*)(Hr + (size_t)s3 * 64);
            sx += (v0.x + v1.x) + (v2.x + v3.x);
            sy += (v0.y + v1.y) + (v2.y + v3.y);
        }
        for (; i < end; i++) {
            int s = g_eidx[i];
            float2 v = *(const float2*)(Hr + (size_t)s * 64);
            sx += v.x; sy += v.y;
        }
        int id = g_ideg[r * N + n];
        float nrm = rsqrtf((float)(id < 1 ? 1 : id));
        ax += nrm * sx;
        ay += nrm * sy;
    }
    int c = lane * 2;
    ax += bias[c]     + bias[64 + c]     + bias[128 + c];
    ay += bias[c + 1] + bias[64 + c + 1] + bias[128 + c + 1];
    if (do_relu) { ax = fmaxf(ax, 0.f); ay = fmaxf(ay, 0.f); }
    *(float2*)(out + (size_t)n * 64 + c) = make_float2(ax, ay);
}

// ---------------- launch ----------------
extern "C" void kernel_launch(void* const* d_in, const int* in_sizes, int n_in,
                              void* d_out, int out_size) {
    const float* x   = (const float*)d_in[0];
    const float* W1  = (const float*)d_in[1];
    const float* b1  = (const float*)d_in[2];
    const float* W2  = (const float*)d_in[3];
    const float* b2  = (const float*)d_in[4];
    const int*   src = (const int*)d_in[5];
    const int*   dst = (const int*)d_in[6];
    float* out = (float*)d_out;

    const int N = in_sizes[0] / FIN1;   // 50000
    const int E = in_sizes[5] / NREL;   // 600000

    float *Hp, *h1p;
    cudaGetSymbolAddress((void**)&Hp,  g_H);
    cudaGetSymbolAddress((void**)&h1p, g_h1);

    const int scanB = (M_SEG + 1023) / 1024;   // 147

    // degrees + CSR (shared by both layers)
    zero_kernel<<<(M_SEG + 255) / 256, 256>>>();
    deg_kernel<<<(NREL * E + 255) / 256, 256>>>(src, dst, E, N);
    scan1_kernel<<<scanB, 256>>>();
    scan2_kernel<<<1, 256>>>(scanB);
    scan3_kernel<<<(M_SEG + 255) / 256, 256>>>(NREL * E);
    fill_kernel<<<(NREL * E + 255) / 256, 256>>>(src, dst, E, N);

    dim3 gemm_grid((N + 127) / 128, NREL);
    int gather_blocks = (N * 32 + 255) / 256;

    // layer 1
    gemm_kernel<FIN1><<<gemm_grid, 128>>>(x, W1, Hp, N);
    gather_kernel<<<gather_blocks, 256>>>(Hp, b1, h1p, N, 1);

    // layer 2
    gemm_kernel<FHID><<<gemm_grid, 128>>>(h1p, W2, Hp, N);
    gather_kernel<<<gather_blocks, 256>>>(Hp, b2, out, N, 0);
}

// round 3
// speedup vs baseline: 1.3010x; 1.0487x over previous
#include <cuda_runtime.h>
#include <cuda_fp16.h>
#include <cstdint>

#define NNODES 50000
#define NREL   3
#define NEDGE  600000
#define FIN1   128
#define FHID   64
#define M_SEG  (NREL * NNODES)      // 150000 segments

// ---------------- scratch (no allocs allowed) ----------------
__device__ __align__(128) __half g_H[(size_t)NREL * NNODES * FHID]; // per-rel GEMM out (19.2MB, fp16)
__device__ __align__(128) float  g_h1[(size_t)NNODES * FHID];       // layer-1 activations (fp32)
__device__ int g_odeg[M_SEG];
__device__ int g_ideg[M_SEG];
__device__ int g_off[M_SEG + 1];     // CSR offsets (by dst, per relation)
__device__ int g_cursor[M_SEG];
__device__ int g_eidx[NREL * NEDGE]; // src node per CSR slot
__device__ int g_bsum[256];          // block sums for scan

// ---------------- degree / CSR build ----------------

__global__ void zero_kernel() {
    int i = blockIdx.x * blockDim.x + threadIdx.x;
    if (i < M_SEG) { g_odeg[i] = 0; g_ideg[i] = 0; }
}

__global__ void deg_kernel(const int* __restrict__ src, const int* __restrict__ dst,
                           int E, int N) {
    int e = blockIdx.x * blockDim.x + threadIdx.x;
    if (e >= NREL * E) return;
    int r = (e >= E) + (e >= 2 * E);
    atomicAdd(&g_odeg[r * N + src[e]], 1);
    atomicAdd(&g_ideg[r * N + dst[e]], 1);
}

// scan phase 1: per-1024-element block exclusive scan + block sums
__global__ void scan1_kernel() {
    __shared__ int sh[256];
    int t = threadIdx.x;
    int base = blockIdx.x * 1024 + t * 4;
    int v0 = (base + 0 < M_SEG) ? g_ideg[base + 0] : 0;
    int v1 = (base + 1 < M_SEG) ? g_ideg[base + 1] : 0;
    int v2 = (base + 2 < M_SEG) ? g_ideg[base + 2] : 0;
    int v3 = (base + 3 < M_SEG) ? g_ideg[base + 3] : 0;
    int t0 = v0, t1 = t0 + v1, t2 = t1 + v2, t3 = t2 + v3;
    sh[t] = t3;
    __syncthreads();
    for (int off = 1; off < 256; off <<= 1) {
        int x = (t >= off) ? sh[t - off] : 0;
        __syncthreads();
        sh[t] += x;
        __syncthreads();
    }
    int excl = (t > 0) ? sh[t - 1] : 0;
    if (base + 0 < M_SEG) g_off[base + 0] = excl;
    if (base + 1 < M_SEG) g_off[base + 1] = excl + t0;
    if (base + 2 < M_SEG) g_off[base + 2] = excl + t1;
    if (base + 3 < M_SEG) g_off[base + 3] = excl + t2;
    if (t == 255) g_bsum[blockIdx.x] = sh[255];
}

// scan phase 2: exclusive scan of block sums (single block, B <= 256)
__global__ void scan2_kernel(int B) {
    __shared__ int sh[256];
    int t = threadIdx.x;
    sh[t] = (t < B) ? g_bsum[t] : 0;
    __syncthreads();
    for (int off = 1; off < 256; off <<= 1) {
        int x = (t >= off) ? sh[t - off] : 0;
        __syncthreads();
        sh[t] += x;
        __syncthreads();
    }
    int excl = (t > 0) ? sh[t - 1] : 0;
    if (t < B) g_bsum[t] = excl;
}

// scan phase 3: add block bases; init cursor; write sentinel
__global__ void scan3_kernel(int totalE) {
    int i = blockIdx.x * blockDim.x + threadIdx.x;
    if (i < M_SEG) {
        int v = g_off[i] + g_bsum[i >> 10];
        g_off[i] = v;
        g_cursor[i] = v;
    }
    if (i == 0) g_off[M_SEG] = totalE;
}

__global__ void fill_kernel(const int* __restrict__ src, const int* __restrict__ dst,
                            int E, int N) {
    int e = blockIdx.x * blockDim.x + threadIdx.x;
    if (e >= NREL * E) return;
    int r = (e >= E) + (e >= 2 * E);
    int pos = atomicAdd(&g_cursor[r * N + dst[e]], 1);
    g_eidx[pos] = src[e];
}

// ---------------- GEMM: H[r][row] = fp16( rsqrt(odeg) * (X[row] @ W[r]) ) ----------
// tile 128 rows x 64 cols, 128 threads, 8x8 per thread, K chunked by 32
template <int FIN>
__global__ void gemm_kernel(const float* __restrict__ X, const float* __restrict__ W,
                            __half* __restrict__ Hout, int N) {
    constexpr int TK = 32;
    constexpr int XS = TK + 4;  // 36 floats/row, float4-aligned
    __shared__ float sX[128 * XS];
    __shared__ float sW[TK * 64];

    const int r    = blockIdx.y;
    const int row0 = blockIdx.x * 128;
    const int tid  = threadIdx.x;     // 0..127
    const int tc   = tid & 7;         // 8 col-groups of 8 cols
    const int tr   = tid >> 3;        // 0..15, rows tr + 16*i

    float acc[8][8] = {};

    for (int kt = 0; kt < FIN; kt += TK) {
        // W chunk [TK x 64] contiguous: 512 float4
        const float4* Wg = (const float4*)(W + ((size_t)r * FIN + kt) * 64);
        #pragma unroll
        for (int i = tid; i < TK * 16; i += 128) ((float4*)sW)[i] = Wg[i];
        // X chunk [128 rows x TK]: 8 float4 per row
        #pragma unroll
        for (int i = tid; i < 128 * (TK / 4); i += 128) {
            int row = i >> 3, c4 = i & 7;
            int grow = row0 + row;
            float4 v = make_float4(0.f, 0.f, 0.f, 0.f);
            if (grow < N) v = __ldg((const float4*)(X + (size_t)grow * FIN + kt) + c4);
            *(float4*)(sX + row * XS + c4 * 4) = v;
        }
        __syncthreads();

        #pragma unroll
        for (int k = 0; k < TK; k++) {
            float a[8];
            #pragma unroll
            for (int i = 0; i < 8; i++) a[i] = sX[(tr + 16 * i) * XS + k];
            float4 b0 = *(const float4*)(sW + k * 64 + tc * 8);
            float4 b1 = *(const float4*)(sW + k * 64 + tc * 8 + 4);
            #pragma unroll
            for (int i = 0; i < 8; i++) {
                acc[i][0] += a[i] * b0.x; acc[i][1] += a[i] * b0.y;
                acc[i][2] += a[i] * b0.z; acc[i][3] += a[i] * b0.w;
                acc[i][4] += a[i] * b1.x; acc[i][5] += a[i] * b1.y;
                acc[i][6] += a[i] * b1.z; acc[i][7] += a[i] * b1.w;
            }
        }
        __syncthreads();
    }

    #pragma unroll
    for (int i = 0; i < 8; i++) {
        int grow = row0 + tr + 16 * i;
        if (grow < N) {
            int od = g_odeg[r * N + grow];
            float s = rsqrtf((float)(od < 1 ? 1 : od));
            union { uint4 u; __half2 h[4]; } p;
            p.h[0] = __floats2half2_rn(acc[i][0] * s, acc[i][1] * s);
            p.h[1] = __floats2half2_rn(acc[i][2] * s, acc[i][3] * s);
            p.h[2] = __floats2half2_rn(acc[i][4] * s, acc[i][5] * s);
            p.h[3] = __floats2half2_rn(acc[i][6] * s, acc[i][7] * s);
            *(uint4*)(Hout + ((size_t)r * N + grow) * 64 + tc * 8) = p.u;
        }
    }
}

// ---------------- gather-aggregate (CSR), fused norm+bias+relu ----------------
// one warp per node; lane owns 2 channels (one half2). Edge ids prefetched
// coalesced by lanes and broadcast via shfl (no dependent-scalar-load chain).
__global__ void gather_kernel(const __half* __restrict__ H, const float* __restrict__ bias,
                              float* __restrict__ out, int N, int do_relu) {
    int warp = (blockIdx.x * blockDim.x + threadIdx.x) >> 5;
    int lane = threadIdx.x & 31;
    if (warp >= N) return;
    const int n = warp;

    float ax = 0.f, ay = 0.f;
    #pragma unroll
    for (int r = 0; r < NREL; r++) {
        const __half2* Hr = (const __half2*)H + (size_t)r * N * 32 + lane;
        int beg = g_off[r * N + n];
        int end = g_off[r * N + n + 1];
        float sx = 0.f, sy = 0.f;
        for (int base = beg; base < end; base += 32) {
            int m = end - base; if (m > 32) m = 32;
            int myid = (lane < m) ? g_eidx[base + lane] : 0;
            int j = 0;
            for (; j + 4 <= m; j += 4) {
                int s0 = __shfl_sync(0xffffffffu, myid, j);
                int s1 = __shfl_sync(0xffffffffu, myid, j + 1);
                int s2 = __shfl_sync(0xffffffffu, myid, j + 2);
                int s3 = __shfl_sync(0xffffffffu, myid, j + 3);
                float2 v0 = __half22float2(Hr[(size_t)s0 * 32]);
                float2 v1 = __half22float2(Hr[(size_t)s1 * 32]);
                float2 v2 = __half22float2(Hr[(size_t)s2 * 32]);
                float2 v3 = __half22float2(Hr[(size_t)s3 * 32]);
                sx += (v0.x + v1.x) + (v2.x + v3.x);
                sy += (v0.y + v1.y) + (v2.y + v3.y);
            }
            for (; j < m; j++) {
                int s = __shfl_sync(0xffffffffu, myid, j);
                float2 v = __half22float2(Hr[(size_t)s * 32]);
                sx += v.x; sy += v.y;
            }
        }
        int id = g_ideg[r * N + n];
        float nrm = rsqrtf((float)(id < 1 ? 1 : id));
        ax += nrm * sx;
        ay += nrm * sy;
    }
    int c = lane * 2;
    ax += bias[c]     + bias[64 + c]     + bias[128 + c];
    ay += bias[c + 1] + bias[64 + c + 1] + bias[128 + c + 1];
    if (do_relu) { ax = fmaxf(ax, 0.f); ay = fmaxf(ay, 0.f); }
    *(float2*)(out + (size_t)n * 64 + c) = make_float2(ax, ay);
}

// ---------------- launch ----------------
extern "C" void kernel_launch(void* const* d_in, const int* in_sizes, int n_in,
                              void* d_out, int out_size) {
    const float* x   = (const float*)d_in[0];
    const float* W1  = (const float*)d_in[1];
    const float* b1  = (const float*)d_in[2];
    const float* W2  = (const float*)d_in[3];
    const float* b2  = (const float*)d_in[4];
    const int*   src = (const int*)d_in[5];
    const int*   dst = (const int*)d_in[6];
    float* out = (float*)d_out;

    const int N = in_sizes[0] / FIN1;   // 50000
    const int E = in_sizes[5] / NREL;   // 600000

    __half* Hp;  float* h1p;
    cudaGetSymbolAddress((void**)&Hp,  g_H);
    cudaGetSymbolAddress((void**)&h1p, g_h1);

    const int scanB = (M_SEG + 1023) / 1024;   // 147

    // degrees + CSR (shared by both layers)
    zero_kernel<<<(M_SEG + 255) / 256, 256>>>();
    deg_kernel<<<(NREL * E + 255) / 256, 256>>>(src, dst, E, N);
    scan1_kernel<<<scanB, 256>>>();
    scan2_kernel<<<1, 256>>>(scanB);
    scan3_kernel<<<(M_SEG + 255) / 256, 256>>>(NREL * E);
    fill_kernel<<<(NREL * E + 255) / 256, 256>>>(src, dst, E, N);

    dim3 gemm_grid((N + 127) / 128, NREL);
    int gather_blocks = (N * 32 + 255) / 256;

    // layer 1
    gemm_kernel<FIN1><<<gemm_grid, 128>>>(x, W1, Hp, N);
    gather_kernel<<<gather_blocks, 256>>>(Hp, b1, h1p, N, 1);

    // layer 2
    gemm_kernel<FHID><<<gemm_grid, 128>>>(h1p, W2, Hp, N);
    gather_kernel<<<gather_blocks, 256>>>(Hp, b2, out, N, 0);
}

// round 6
// speedup vs baseline: 1.3307x; 1.0228x over previous
#include <cuda_runtime.h>
#include <cuda_fp16.h>
#include <mma.h>
#include <cstdint>
using namespace nvcuda;

#define NNODES 50000
#define NPAD   50048          // padded to multiple of 32 for wmma tiles
#define NREL   3
#define NEDGE  600000
#define FIN1   128
#define FHID   64
#define M_SEG  (NREL * NNODES)

// ---------------- scratch (no allocs allowed) ----------------
__device__ __align__(128) __half g_xh[(size_t)NPAD * FIN1];          // x in fp16 (12.8MB)
__device__ __align__(128) __half g_w1h[NREL * FIN1 * FHID];
__device__ __align__(128) __half g_w2h[NREL * FHID * FHID];
__device__ __align__(128) __half g_H[(size_t)NREL * NPAD * FHID];    // per-rel GEMM out (19.2MB)
__device__ __align__(128) __half g_h1h[(size_t)NPAD * FHID];         // layer-1 activations fp16
__device__ int g_odeg[M_SEG];
__device__ int g_ideg[M_SEG];
__device__ int g_off[M_SEG + 1];
__device__ int g_cursor[M_SEG];
__device__ int g_eidx[NREL * NEDGE];
__device__ int g_bsum[256];

// ---------------- init / degrees / CSR ----------------

__global__ void zero_kernel() {
    int i = blockIdx.x * blockDim.x + threadIdx.x;
    if (i < M_SEG) { g_odeg[i] = 0; g_ideg[i] = 0; }
    // zero pad rows of h1h (rows NNODES..NPAD-1), 48*32 half2
    if (i < (NPAD - NNODES) * 32)
        ((__half2*)g_h1h)[(size_t)NNODES * 32 + i] = __floats2half2_rn(0.f, 0.f);
}

__global__ void convert_x(const float* __restrict__ x) {
    int i = blockIdx.x * blockDim.x + threadIdx.x;    // one thread = 8 halves
    if (i >= NPAD * (FIN1 / 8)) return;
    size_t gi = (size_t)i * 8;
    int row = (int)(gi >> 7);                         // FIN1 = 128
    union { uint4 u; __half2 h[4]; } p;
    if (row < NNODES) {
        float4 a = *(const float4*)(x + gi);
        float4 b = *(const float4*)(x + gi + 4);
        p.h[0] = __floats2half2_rn(a.x, a.y);
        p.h[1] = __floats2half2_rn(a.z, a.w);
        p.h[2] = __floats2half2_rn(b.x, b.y);
        p.h[3] = __floats2half2_rn(b.z, b.w);
    } else {
        p.h[0] = p.h[1] = p.h[2] = p.h[3] = __floats2half2_rn(0.f, 0.f);
    }
    *(uint4*)(g_xh + gi) = p.u;
}

__global__ void convert_w(const float* __restrict__ W1, const float* __restrict__ W2) {
    int i = blockIdx.x * blockDim.x + threadIdx.x;
    const int T1 = NREL * FIN1 * FHID;               // 24576
    const int T2 = NREL * FHID * FHID;               // 12288
    if (i < T1) g_w1h[i] = __float2half_rn(W1[i]);
    else if (i < T1 + T2) g_w2h[i - T1] = __float2half_rn(W2[i - T1]);
}

__global__ void deg_kernel(const int* __restrict__ src, const int* __restrict__ dst,
                           int E, int N) {
    int e = blockIdx.x * blockDim.x + threadIdx.x;
    if (e >= NREL * E) return;
    int r = (e >= E) + (e >= 2 * E);
    atomicAdd(&g_odeg[r * N + src[e]], 1);
    atomicAdd(&g_ideg[r * N + dst[e]], 1);
}

__global__ void scan1_kernel() {
    __shared__ int sh[256];
    int t = threadIdx.x;
    int base = blockIdx.x * 1024 + t * 4;
    int v0 = (base + 0 < M_SEG) ? g_ideg[base + 0] : 0;
    int v1 = (base + 1 < M_SEG) ? g_ideg[base + 1] : 0;
    int v2 = (base + 2 < M_SEG) ? g_ideg[base + 2] : 0;
    int v3 = (base + 3 < M_SEG) ? g_ideg[base + 3] : 0;
    int t0 = v0, t1 = t0 + v1, t2 = t1 + v2, t3 = t2 + v3;
    sh[t] = t3;
    __syncthreads();
    for (int off = 1; off < 256; off <<= 1) {
        int x = (t >= off) ? sh[t - off] : 0;
        __syncthreads();
        sh[t] += x;
        __syncthreads();
    }
    int excl = (t > 0) ? sh[t - 1] : 0;
    if (base + 0 < M_SEG) g_off[base + 0] = excl;
    if (base + 1 < M_SEG) g_off[base + 1] = excl + t0;
    if (base + 2 < M_SEG) g_off[base + 2] = excl + t1;
    if (base + 3 < M_SEG) g_off[base + 3] = excl + t2;
    if (t == 255) g_bsum[blockIdx.x] = sh[255];
}

__global__ void scan2_kernel(int B) {
    __shared__ int sh[256];
    int t = threadIdx.x;
    sh[t] = (t < B) ? g_bsum[t] : 0;
    __syncthreads();
    for (int off = 1; off < 256; off <<= 1) {
        int x = (t >= off) ? sh[t - off] : 0;
        __syncthreads();
        sh[t] += x;
        __syncthreads();
    }
    int excl = (t > 0) ? sh[t - 1] : 0;
    if (t < B) g_bsum[t] = excl;
}

__global__ void scan3_kernel(int totalE) {
    int i = blockIdx.x * blockDim.x + threadIdx.x;
    if (i < M_SEG) {
        int v = g_off[i] + g_bsum[i >> 10];
        g_off[i] = v;
        g_cursor[i] = v;
    }
    if (i == 0) g_off[M_SEG] = totalE;
}

__global__ void fill_kernel(const int* __restrict__ src, const int* __restrict__ dst,
                            int E, int N) {
    int e = blockIdx.x * blockDim.x + threadIdx.x;
    if (e >= NREL * E) return;
    int r = (e >= E) + (e >= 2 * E);
    int pos = atomicAdd(&g_cursor[r * N + dst[e]], 1);
    g_eidx[pos] = src[e];
}

// ---------------- tensor-core GEMM: H[r][row] = fp16(rsqrt(odeg)*(X@W[r])) -----
// block: 256 thr = 8 warps = 2 m-tiles x 4 n-tiles; block tile M=32, N=64.
template <int K>
__global__ void gemm_tc(const __half* __restrict__ Xh, const __half* __restrict__ Wh,
                        __half* __restrict__ Hout, int N) {
    __shared__ float sC[32 * 72];
    const int r    = blockIdx.y;
    const int row0 = blockIdx.x * 32;
    const int wid  = threadIdx.x >> 5;
    const int msub = wid >> 2, nsub = wid & 3;

    wmma::fragment<wmma::accumulator, 16, 16, 16, float> c;
    wmma::fill_fragment(c, 0.0f);
    const __half* A = Xh + (size_t)(row0 + msub * 16) * K;
    const __half* B = Wh + (size_t)r * K * 64 + nsub * 16;
    #pragma unroll
    for (int k0 = 0; k0 < K; k0 += 16) {
        wmma::fragment<wmma::matrix_a, 16, 16, 16, __half, wmma::row_major> a;
        wmma::fragment<wmma::matrix_b, 16, 16, 16, __half, wmma::row_major> b;
        wmma::load_matrix_sync(a, A + k0, K);
        wmma::load_matrix_sync(b, B + (size_t)k0 * 64, 64);
        wmma::mma_sync(c, a, b, c);
    }
    wmma::store_matrix_sync(sC + msub * 16 * 72 + nsub * 16, c, 72, wmma::mem_row_major);
    __syncthreads();

    #pragma unroll
    for (int i = threadIdx.x; i < 32 * 32; i += 256) {
        int row = i >> 5, c2 = i & 31;
        int grow = row0 + row;
        if (grow < N) {
            int od = g_odeg[r * N + grow];
            float s = rsqrtf((float)(od < 1 ? 1 : od));
            float v0 = sC[row * 72 + c2 * 2];
            float v1 = sC[row * 72 + c2 * 2 + 1];
            ((__half2*)Hout)[((size_t)r * NPAD + grow) * 32 + c2] =
                __floats2half2_rn(v0 * s, v1 * s);
        }
    }
}

// ---------------- gather-aggregate (CSR), fused norm+bias+relu ----------------
// one warp per node; lane owns 2 channels. unroll-8 edge-row prefetch.
template <bool HALF_OUT>
__global__ void gather_kernel(const __half* __restrict__ H, const float* __restrict__ bias,
                              void* __restrict__ outp, int N) {
    int warp = (blockIdx.x * blockDim.x + threadIdx.x) >> 5;
    int lane = threadIdx.x & 31;
    if (warp >= N) return;
    const int n = warp;

    float ax = 0.f, ay = 0.f;
    #pragma unroll
    for (int r = 0; r < NREL; r++) {
        const __half2* Hr = (const __half2*)H + (size_t)r * NPAD * 32 + lane;
        int beg = g_off[r * N + n];
        int end = g_off[r * N + n + 1];
        float sx = 0.f, sy = 0.f;
        for (int base = beg; base < end; base += 32) {
            int m = end - base; if (m > 32) m = 32;
            int myid = (lane < m) ? g_eidx[base + lane] : 0;
            int j = 0;
            for (; j + 8 <= m; j += 8) {
                int s0 = __shfl_sync(0xffffffffu, myid, j);
                int s1 = __shfl_sync(0xffffffffu, myid, j + 1);
                int s2 = __shfl_sync(0xffffffffu, myid, j + 2);
                int s3 = __shfl_sync(0xffffffffu, myid, j + 3);
                int s4 = __shfl_sync(0xffffffffu, myid, j + 4);
                int s5 = __shfl_sync(0xffffffffu, myid, j + 5);
                int s6 = __shfl_sync(0xffffffffu, myid, j + 6);
                int s7 = __shfl_sync(0xffffffffu, myid, j + 7);
                float2 v0 = __half22float2(Hr[(size_t)s0 * 32]);
                float2 v1 = __half22float2(Hr[(size_t)s1 * 32]);
                float2 v2 = __half22float2(Hr[(size_t)s2 * 32]);
                float2 v3 = __half22float2(Hr[(size_t)s3 * 32]);
                float2 v4 = __half22float2(Hr[(size_t)s4 * 32]);
                float2 v5 = __half22float2(Hr[(size_t)s5 * 32]);
                float2 v6 = __half22float2(Hr[(size_t)s6 * 32]);
                float2 v7 = __half22float2(Hr[(size_t)s7 * 32]);
                sx += ((v0.x + v1.x) + (v2.x + v3.x)) + ((v4.x + v5.x) + (v6.x + v7.x));
                sy += ((v0.y + v1.y) + (v2.y + v3.y)) + ((v4.y + v5.y) + (v6.y + v7.y));
            }
            for (; j < m; j++) {
                int s = __shfl_sync(0xffffffffu, myid, j);
                float2 v = __half22float2(Hr[(size_t)s * 32]);
                sx += v.x; sy += v.y;
            }
        }
        int id = g_ideg[r * N + n];
        float nrm = rsqrtf((float)(id < 1 ? 1 : id));
        ax += nrm * sx;
        ay += nrm * sy;
    }
    int c = lane * 2;
    ax += bias[c]     + bias[64 + c]     + bias[128 + c];
    ay += bias[c + 1] + bias[64 + c + 1] + bias[128 + c + 1];
    if (HALF_OUT) {   // layer 1: relu + fp16 store
        ax = fmaxf(ax, 0.f); ay = fmaxf(ay, 0.f);
        ((__half2*)outp)[(size_t)n * 32 + lane] = __floats2half2_rn(ax, ay);
    } else {          // layer 2: fp32 store
        *(float2*)((float*)outp + (size_t)n * 64 + c) = make_float2(ax, ay);
    }
}

// ---------------- launch ----------------
extern "C" void kernel_launch(void* const* d_in, const int* in_sizes, int n_in,
                              void* d_out, int out_size) {
    const float* x   = (const float*)d_in[0];
    const float* W1  = (const float*)d_in[1];
    const float* b1  = (const float*)d_in[2];
    const float* W2  = (const float*)d_in[3];
    const float* b2  = (const float*)d_in[4];
    const int*   src = (const int*)d_in[5];
    const int*   dst = (const int*)d_in[6];
    float* out = (float*)d_out;

    const int N = in_sizes[0] / FIN1;   // 50000
    const int E = in_sizes[5] / NREL;   // 600000

    __half *Hp, *xh, *w1h, *w2h, *h1h;
    cudaGetSymbolAddress((void**)&Hp,  g_H);
    cudaGetSymbolAddress((void**)&xh,  g_xh);
    cudaGetSymbolAddress((void**)&w1h, g_w1h);
    cudaGetSymbolAddress((void**)&w2h, g_w2h);
    cudaGetSymbolAddress((void**)&h1h, g_h1h);

    const int scanB = (M_SEG + 1023) / 1024;   // 147

    zero_kernel<<<(M_SEG + 255) / 256, 256>>>();
    convert_x<<<(NPAD * (FIN1 / 8) + 255) / 256, 256>>>(x);
    convert_w<<<(NREL * (FIN1 + FHID) * FHID + 255) / 256, 256>>>(W1, W2);
    deg_kernel<<<(NREL * E + 255) / 256, 256>>>(src, dst, E, N);
    scan1_kernel<<<scanB, 256>>>();
    scan2_kernel<<<1, 256>>>(scanB);
    scan3_kernel<<<(M_SEG + 255) / 256, 256>>>(NREL * E);
    fill_kernel<<<(NREL * E + 255) / 256, 256>>>(src, dst, E, N);

    dim3 gemm_grid(NPAD / 32, NREL);
    int gather_blocks = (N * 32 + 255) / 256;

    // layer 1
    gemm_tc<FIN1><<<gemm_grid, 256>>>(xh, w1h, Hp, N);
    gather_kernel<true><<<gather_blocks, 256>>>(Hp, b1, h1h, N);

    // layer 2
    gemm_tc<FHID><<<gemm_grid, 256>>>(h1h, w2h, Hp, N);
    gather_kernel<false><<<gather_blocks, 256>>>(Hp, b2, out, N);
}